// round 15
// baseline (speedup 1.0000x reference)
#include <cuda_runtime.h>
#include <cuda_bf16.h>
#include <cstdint>

#define BB 16384
#define DD 256
#define KK 3000
#define KPAD 3072
#define KS 3072          // padded row stride of g_E/g_P (elements)
#define NFB2 1024        // fused row/col blocks over ALL 2B rows
#define RPB 32           // rows per fused block
#define RFB 8            // row-pairs per final block

#define C_EXP20 28.853900817779268f   // 20/ln2
#define C_EXP10 14.426950408889634f   // 10/ln2
#define C_LN2   0.6931471805599453f

// ---------------- device scratch -------------------------------------------
__device__ __align__(16) __nv_bfloat16 g_A2[(size_t)2 * BB * DD];
__device__ __align__(16) __nv_bfloat16 g_B2[(size_t)KPAD * DD];
__device__ __align__(16) __nv_bfloat16 g_E[(size_t)2 * BB * KS];  // exp(sim/eps) bf16
__device__ __align__(16) __nv_bfloat16 g_P[(size_t)2 * BB * KS];  // sim bf16
__device__ float g_partW[(size_t)256 * KPAD];    // per-GEMM-mtile col partials
__device__ float g_part2[(size_t)NFB2 * KPAD];   // fused-pass col partials
__device__ float g_W[2 * KPAD];                  // holds u = 1/(K*W)
__device__ float2 g_ul[2 * KK];                  // (u, log u) per loss (final iter)
__device__ float g_rowloss[BB];

// ---------------- helpers ----------------------------------------------------
static __device__ __forceinline__ float ex2f(float x) {
    float y; asm("ex2.approx.ftz.f32 %0, %1;" : "=f"(y) : "f"(x)); return y;
}
static __device__ __forceinline__ uint32_t s2u(const void* p) {
    uint32_t a;
    asm("{ .reg .u64 t; cvta.to.shared.u64 t, %1; cvt.u32.u64 %0, t; }" : "=r"(a) : "l"(p));
    return a;
}

#define LDSM4(r, a)                                                             \
    asm volatile("ldmatrix.sync.aligned.m8n8.x4.shared.b16 {%0,%1,%2,%3}, [%4];" \
                 : "=r"((r)[0]), "=r"((r)[1]), "=r"((r)[2]), "=r"((r)[3]) : "r"(a))

#define MMA16816(d, a, b)                                                       \
    asm volatile(                                                               \
        "mma.sync.aligned.m16n8k16.row.col.f32.bf16.bf16.f32 "                  \
        "{%0,%1,%2,%3}, {%4,%5,%6,%7}, {%8,%9}, {%0,%1,%2,%3};"                 \
        : "+f"((d)[0]), "+f"((d)[1]), "+f"((d)[2]), "+f"((d)[3])                \
        : "r"((a)[0]), "r"((a)[1]), "r"((a)[2]), "r"((a)[3]),                   \
          "r"((b)[0]), "r"((b)[1]))

#define CPASYNC16(dst, src) \
    asm volatile("cp.async.cg.shared.global [%0], [%1], 16;" :: "r"(dst), "l"(src))
#define CP_COMMIT()  asm volatile("cp.async.commit_group;" ::: "memory")
#define CP_WAIT(n)   asm volatile("cp.async.wait_group %0;" :: "n"(n) : "memory")

// ---------------- 1) L2 normalize (q,k,c) + pad, one launch ------------------
__global__ void l2norm_all_kernel(const float* __restrict__ q,
                                  const float* __restrict__ k,
                                  const float* __restrict__ c) {
    int row  = blockIdx.x * 8 + (threadIdx.x >> 5);
    int lane = threadIdx.x & 31;
    if (row >= 2 * BB + KPAD) return;

    const float* src;
    __nv_bfloat16* dst;
    if (row < BB)            { src = q + (size_t)row * DD;            dst = g_A2 + (size_t)row * DD; }
    else if (row < 2 * BB)   { src = k + (size_t)(row - BB) * DD;     dst = g_A2 + (size_t)row * DD; }
    else if (row < 2 * BB + KK) { src = c + (size_t)(row - 2 * BB) * DD; dst = g_B2 + (size_t)(row - 2 * BB) * DD; }
    else {
        dst = g_B2 + (size_t)(row - 2 * BB) * DD;
#pragma unroll
        for (int i = 0; i < 8; i++) dst[lane + 32 * i] = __float2bfloat16(0.0f);
        return;
    }
    float v[8]; float s = 0.0f;
#pragma unroll
    for (int i = 0; i < 8; i++) { v[i] = src[lane + 32 * i]; s += v[i] * v[i]; }
#pragma unroll
    for (int o = 16; o > 0; o >>= 1) s += __shfl_xor_sync(0xffffffffu, s, o);
    float inv = 1.0f / fmaxf(sqrtf(s), 1e-12f);
#pragma unroll
    for (int i = 0; i < 8; i++) dst[lane + 32 * i] = __float2bfloat16(v[i] * inv);
}

// ---------------- 2) GEMM 128x256 tile + fused epilogue (E, P, W1) -----------
#define GSTAGE 3
#define STAGE_BYTES 49152   // A 16KB + B 32KB
#define NIT (DD / 64)       // 4

__global__ __launch_bounds__(256) void gemm_mma_kernel() {
    extern __shared__ char smem[];
    const uint32_t sb = s2u(smem);
    const int tid = threadIdx.x;
    const int lane = tid & 31;
    const int wid = tid >> 5;
    const int wm = wid >> 2;
    const int wn = wid & 3;

    const int nTilesN = KPAD / 256;   // 12
    const int mBase = (int)(blockIdx.x / nTilesN) * 128;
    const int nBase = (int)(blockIdx.x % nTilesN) * 256;

    const __nv_bfloat16* gA = g_A2 + (size_t)mBase * DD;
    const __nv_bfloat16* gB = g_B2 + (size_t)nBase * DD;

    float acc[4][8][4] = {};

    auto load_stage = [&](int s, int kIter) {
        uint32_t so = sb + (uint32_t)s * STAGE_BYTES;
        int k0 = kIter * 64;
#pragma unroll
        for (int i = 0; i < 12; i++) {
            int q = tid + i * 256;
            int isB = (q >= 1024);
            int idx = isB ? (q - 1024) : q;
            int row = idx >> 3;
            int c = idx & 7;
            uint32_t dst = so + (isB ? 16384 : 0) + row * 128 + ((c ^ (row & 7)) << 4);
            const __nv_bfloat16* src = isB ? (gB + (size_t)row * DD + k0 + c * 8)
                                           : (gA + (size_t)row * DD + k0 + c * 8);
            CPASYNC16(dst, src);
        }
        CP_COMMIT();
    };

    load_stage(0, 0);
    load_stage(1, 1);

    for (int it = 0; it < NIT; it++) {
        if (it + 2 < NIT) CP_WAIT(1);
        else              CP_WAIT(0);
        __syncthreads();
        if (it + 2 < NIT) load_stage((it + 2) % GSTAGE, it + 2);

        uint32_t aB = sb + (uint32_t)(it % GSTAGE) * STAGE_BYTES;
        uint32_t bB = aB + 16384;
#pragma unroll
        for (int ks = 0; ks < 4; ks++) {
            uint32_t a[4][4], b[8][2];
            int cch = ks * 2 + (lane >> 4);
#pragma unroll
            for (int mi = 0; mi < 4; mi++) {
                int row = wm * 64 + mi * 16 + (lane & 15);
                uint32_t addr = aB + row * 128 + ((cch ^ (row & 7)) << 4);
                LDSM4(a[mi], addr);
            }
#pragma unroll
            for (int nj = 0; nj < 4; nj++) {
                int row = wn * 64 + nj * 16 + (lane & 15);
                uint32_t addr = bB + row * 128 + ((cch ^ (row & 7)) << 4);
                uint32_t r4[4];
                LDSM4(r4, addr);
                b[nj * 2][0]     = r4[0]; b[nj * 2][1]     = r4[2];
                b[nj * 2 + 1][0] = r4[1]; b[nj * 2 + 1][1] = r4[3];
            }
#pragma unroll
            for (int mi = 0; mi < 4; mi++)
#pragma unroll
                for (int ni = 0; ni < 8; ni++)
                    MMA16816(acc[mi][ni], a[mi], b[ni]);
        }
        __syncthreads();
    }

    // fused epilogue: E bf16 + P bf16 (zero-padded cols) + per-tile colsums of E
    float* cs = (float*)smem;   // [2][256]
    float cp0[8], cp1[8];
#pragma unroll
    for (int ni = 0; ni < 8; ni++) { cp0[ni] = 0.f; cp1[ni] = 0.f; }

#pragma unroll
    for (int ni = 0; ni < 8; ni++) {
        int gn = nBase + wn * 64 + ni * 8 + (lane & 3) * 2;
        bool ok = (gn < KK);
#pragma unroll
        for (int mi = 0; mi < 4; mi++) {
            int gm = mBase + wm * 64 + mi * 16 + (lane >> 2);
            float a0 = acc[mi][ni][0], a1 = acc[mi][ni][1];
            float a2 = acc[mi][ni][2], a3 = acc[mi][ni][3];
            float e0 = ex2f(a0 * C_EXP20), e1 = ex2f(a1 * C_EXP20);
            float e2 = ex2f(a2 * C_EXP20), e3 = ex2f(a3 * C_EXP20);
            if (!ok) { e0 = e1 = e2 = e3 = 0.f; a0 = a1 = a2 = a3 = 0.f; }
            __nv_bfloat162 eh0 = __floats2bfloat162_rn(e0, e1);
            __nv_bfloat162 eh1 = __floats2bfloat162_rn(e2, e3);
            __nv_bfloat162 ph0 = __floats2bfloat162_rn(a0, a1);
            __nv_bfloat162 ph1 = __floats2bfloat162_rn(a2, a3);
            *(uint32_t*)&g_E[(size_t)gm * KS + gn]       = *(uint32_t*)&eh0;
            *(uint32_t*)&g_E[(size_t)(gm + 8) * KS + gn] = *(uint32_t*)&eh1;
            *(uint32_t*)&g_P[(size_t)gm * KS + gn]       = *(uint32_t*)&ph0;
            *(uint32_t*)&g_P[(size_t)(gm + 8) * KS + gn] = *(uint32_t*)&ph1;
            cp0[ni] += e0 + e2;
            cp1[ni] += e1 + e3;
        }
    }
#pragma unroll
    for (int ni = 0; ni < 8; ni++) {
#pragma unroll
        for (int o = 4; o < 32; o <<= 1) {
            cp0[ni] += __shfl_xor_sync(0xffffffffu, cp0[ni], o);
            cp1[ni] += __shfl_xor_sync(0xffffffffu, cp1[ni], o);
        }
        if (lane < 4) {
            cs[wm * 256 + wn * 64 + ni * 8 + lane * 2]     = cp0[ni];
            cs[wm * 256 + wn * 64 + ni * 8 + lane * 2 + 1] = cp1[ni];
        }
    }
    __syncthreads();
    {
        int mtile = (int)(blockIdx.x / nTilesN);
        g_partW[(size_t)mtile * KPAD + nBase + tid] = cs[tid] + cs[256 + tid];
    }
}

// ---------------- 3) slab reductions (write u = 1/(K*W)) ---------------------
__global__ void reduce_w_epi_kernel() {   // grid (6,2), block (128,4)
    int l = blockIdx.y;
    int halfStart = (l == 0) ? 128 : 0;
    int tx = threadIdx.x, ty = threadIdx.y;
    int k4 = (blockIdx.x * 128 + tx) * 4;
    __shared__ float4 sm[4][128];
    float4 s = make_float4(0.f, 0.f, 0.f, 0.f);
    if (k4 < KK) {
        const float* base = g_partW + (size_t)(halfStart + ty * 32) * KPAD + k4;
#pragma unroll 8
        for (int i = 0; i < 32; i++) {
            float4 p = *(const float4*)(base + (size_t)i * KPAD);
            s.x += p.x; s.y += p.y; s.z += p.z; s.w += p.w;
        }
    }
    sm[ty][tx] = s;
    __syncthreads();
    if (ty == 0 && k4 < KK) {
#pragma unroll
        for (int w = 1; w < 4; w++) {
            float4 p = sm[w][tx];
            s.x += p.x; s.y += p.y; s.z += p.z; s.w += p.w;
        }
        float4 u = make_float4(1.0f / ((float)KK * s.x), 1.0f / ((float)KK * s.y),
                               1.0f / ((float)KK * s.z), 1.0f / ((float)KK * s.w));
        *(float4*)&g_W[l * KPAD + k4] = u;
    }
}

__global__ void reduce_w_fused_kernel(int writeU) {   // grid (6,2), block (128,8)
    int l = blockIdx.y;
    int slabStart = (l == 0) ? 512 : 0;
    int tx = threadIdx.x, ty = threadIdx.y;
    int k4 = (blockIdx.x * 128 + tx) * 4;
    __shared__ float4 sm[8][128];
    float4 s = make_float4(0.f, 0.f, 0.f, 0.f);
    if (k4 < KK) {
        const float* base = g_part2 + (size_t)(slabStart + ty * 64) * KPAD + k4;
#pragma unroll 8
        for (int i = 0; i < 64; i++) {
            float4 p = *(const float4*)(base + (size_t)i * KPAD);
            s.x += p.x; s.y += p.y; s.z += p.z; s.w += p.w;
        }
    }
    sm[ty][tx] = s;
    __syncthreads();
    if (ty == 0 && k4 < KK) {
#pragma unroll
        for (int w = 1; w < 8; w++) {
            float4 p = sm[w][tx];
            s.x += p.x; s.y += p.y; s.z += p.z; s.w += p.w;
        }
        float u0 = 1.0f / ((float)KK * s.x), u1 = 1.0f / ((float)KK * s.y);
        float u2 = 1.0f / ((float)KK * s.z), u3 = 1.0f / ((float)KK * s.w);
        *(float4*)&g_W[l * KPAD + k4] = make_float4(u0, u1, u2, u3);
        if (writeU) {
            g_ul[l * KK + k4]     = make_float2(u0, logf(u0));
            g_ul[l * KK + k4 + 1] = make_float2(u1, logf(u1));
            g_ul[l * KK + k4 + 2] = make_float2(u2, logf(u2));
            g_ul[l * KK + k4 + 3] = make_float2(u3, logf(u3));
        }
    }
}

// ---------------- 4) fused row+col pass: register-prefetch pipeline ----------
__global__ __launch_bounds__(256) void fused_rc_kernel() {
    __shared__ __nv_bfloat162 su2[KS / 2];                   // 6 KB
    __shared__ __align__(16) __nv_bfloat16 stage[4 * KS];    // 24 KB
    __shared__ float smw[8];
    __shared__ float sv[4];
    int tid = threadIdx.x, lane = tid & 31, wid = tid >> 5;
    int rowInR = wid >> 1;
    int half = wid & 1;
    int rbase = (int)blockIdx.x * RPB;
    int l = (rbase >= BB) ? 0 : 1;
    const float* U = g_W + (size_t)l * KPAD;
    for (int i = tid; i < KS / 2; i += 256) {
        float a = (2 * i < KK) ? U[2 * i] : 0.f;
        float b = (2 * i + 1 < KK) ? U[2 * i + 1] : 0.f;
        su2[i] = __floats2bfloat162_rn(a, b);
    }

    float acc[12];
#pragma unroll
    for (int i = 0; i < 12; i++) acc[i] = 0.f;

    uint4 v[6];
    {
        const __nv_bfloat16* row = g_E + (size_t)(rbase + rowInR) * KS + half * 1536;
#pragma unroll
        for (int j = 0; j < 6; j++) v[j] = *(const uint4*)(row + (lane + j * 32) * 8);
    }
    __syncthreads();

    for (int r = 0; r < RPB / 4; r++) {
        float m = 0.f;
#pragma unroll
        for (int j = 0; j < 6; j++) {
            int eo = (lane + j * 32) * 8;
            *(uint4*)&stage[rowInR * KS + half * 1536 + eo] = v[j];
            const __nv_bfloat162* h = (const __nv_bfloat162*)&v[j];
            const __nv_bfloat162* up = &su2[(half * 1536 + eo) >> 1];
            uint2 ur0 = *(const uint2*)up;
            uint2 ur1 = *(const uint2*)(up + 2);
#pragma unroll
            for (int t = 0; t < 4; t++) {
                float2 e = __bfloat1622float2(h[t]);
                uint32_t ub = (t < 2) ? ((t == 0) ? ur0.x : ur0.y)
                                      : ((t == 2) ? ur1.x : ur1.y);
                float2 u = __bfloat1622float2(*(__nv_bfloat162*)&ub);
                m += e.x * u.x + e.y * u.y;
            }
        }
#pragma unroll
        for (int o = 16; o > 0; o >>= 1) m += __shfl_xor_sync(0xffffffffu, m, o);
        if (lane == 0) smw[wid] = m;

        if (r + 1 < RPB / 4) {
            const __nv_bfloat16* row =
                g_E + (size_t)(rbase + (r + 1) * 4 + rowInR) * KS + half * 1536;
#pragma unroll
            for (int j = 0; j < 6; j++) v[j] = *(const uint4*)(row + (lane + j * 32) * 8);
        }
        __syncthreads();
        if (tid < 4) sv[tid] = 1.0f / ((float)BB * (smw[2 * tid] + smw[2 * tid + 1]));
        __syncthreads();

#pragma unroll
        for (int rr = 0; rr < 4; rr++) {
            float vv = sv[rr];
            const __nv_bfloat16* sp = &stage[rr * KS + tid * 12];
#pragma unroll
            for (int j = 0; j < 3; j++) {
                uint2 raw = *(const uint2*)(sp + j * 4);
                float2 e0 = __bfloat1622float2(*(__nv_bfloat162*)&raw.x);
                float2 e1 = __bfloat1622float2(*(__nv_bfloat162*)&raw.y);
                acc[j * 4 + 0] += vv * e0.x;
                acc[j * 4 + 1] += vv * e0.y;
                acc[j * 4 + 2] += vv * e1.x;
                acc[j * 4 + 3] += vv * e1.y;
            }
        }
        __syncthreads();
    }

    float* dst = &g_part2[(size_t)blockIdx.x * KPAD + tid * 12];
    *(float4*)(dst)     = make_float4(acc[0], acc[1], acc[2], acc[3]);
    *(float4*)(dst + 4) = make_float4(acc[4], acc[5], acc[6], acc[7]);
    *(float4*)(dst + 8) = make_float4(acc[8], acc[9], acc[10], acc[11]);
}

// ---------------- 5) final: E+P double-buffered, no logs ---------------------
#define FP_SEG 6144              // bytes per row (KS bf16)
#define FP_BUF (4 * FP_SEG)      // Eq | Ek | Pq | Pk
#define FP_SMEM (2 * FP_BUF)     // 49152

__global__ __launch_bounds__(256) void final_pair_kernel() {
    extern __shared__ char fsm[];
    __shared__ float red[32];
    int tid = threadIdx.x, lane = tid & 31, wid = tid >> 5;
    int r0 = (int)blockIdx.x * RFB;

    float4 uu0[6], uu1[6];
    const float4* ulp0 = (const float4*)(g_ul);
    const float4* ulp1 = (const float4*)(g_ul + KK);
#pragma unroll
    for (int i = 0; i < 6; i++) {
        int p2 = tid + 256 * i;
        bool in = (p2 < KK / 2);
        uu0[i] = in ? ulp0[p2] : make_float4(0.f, 0.f, 0.f, 0.f);
        uu1[i] = in ? ulp1[p2] : make_float4(0.f, 0.f, 0.f, 0.f);
    }
    const float M2 = C_EXP10;   // sim <= ~1 -> 10*sim/ln2 <= 14.43

    auto issueF = [&](int j, int buf) {
        int rr = r0 + j;
        const char* sEq = (const char*)(g_E + (size_t)rr * KS);
        const char* sEk = (const char*)(g_E + (size_t)(BB + rr) * KS);
        const char* sPq = (const char*)(g_P + (size_t)rr * KS);
        const char* sPk = (const char*)(g_P + (size_t)(BB + rr) * KS);
        uint32_t d = s2u(fsm) + (uint32_t)buf * FP_BUF;
#pragma unroll
        for (int i = 0; i < 6; i++) {
            int c = tid + 256 * i;        // 0..1535; 384 16B chunks per row
            int seg = c / 384, off = c - seg * 384;
            const char* s = (seg < 2) ? ((seg == 0) ? sEq : sEk)
                                      : ((seg == 2) ? sPq : sPk);
            CPASYNC16(d + seg * FP_SEG + off * 16, s + off * 16);
        }
        CP_COMMIT();
    };

    issueF(0, 0);

    for (int j = 0; j < RFB; j++) {
        if (j + 1 < RFB) { issueF(j + 1, (j + 1) & 1); CP_WAIT(1); }
        else             { CP_WAIT(0); }
        __syncthreads();
        const char* buf = fsm + (size_t)(j & 1) * FP_BUF;
        const __nv_bfloat162* Eq = (const __nv_bfloat162*)(buf);
        const __nv_bfloat162* Ek = (const __nv_bfloat162*)(buf + FP_SEG);
        const __nv_bfloat162* Pq = (const __nv_bfloat162*)(buf + 2 * FP_SEG);
        const __nv_bfloat162* Pk = (const __nv_bfloat162*)(buf + 3 * FP_SEG);

        float a0 = 0.f, a1 = 0.f, s0 = 0.f, s1 = 0.f;
#pragma unroll
        for (int i = 0; i < 6; i++) {
            int p2 = tid + 256 * i;
            if (p2 < KK / 2) {
                float2 eq = __bfloat1622float2(Eq[p2]);
                float2 ek = __bfloat1622float2(Ek[p2]);
                float2 pq = __bfloat1622float2(Pq[p2]);
                float2 pk = __bfloat1622float2(Pk[p2]);
                a0 += uu0[i].x * ek.x + uu0[i].z * ek.y;
                a1 += uu1[i].x * eq.x + uu1[i].z * eq.y;
                s0 += ex2f(fmaf(pq.x, C_EXP10, -M2)) + ex2f(fmaf(pq.y, C_EXP10, -M2));
                s1 += ex2f(fmaf(pk.x, C_EXP10, -M2)) + ex2f(fmaf(pk.y, C_EXP10, -M2));
            }
        }
#pragma unroll
        for (int o = 16; o > 0; o >>= 1) {
            a0 += __shfl_xor_sync(0xffffffffu, a0, o);
            a1 += __shfl_xor_sync(0xffffffffu, a1, o);
            s0 += __shfl_xor_sync(0xffffffffu, s0, o);
            s1 += __shfl_xor_sync(0xffffffffu, s1, o);
        }
        if (lane == 0) { red[wid] = a0; red[8 + wid] = a1; red[16 + wid] = s0; red[24 + wid] = s1; }
        __syncthreads();
        float Mb0 = 0.f, Mb1 = 0.f, se0 = 0.f, se1 = 0.f;
#pragma unroll
        for (int w = 0; w < 8; w++) {
            Mb0 += red[w]; Mb1 += red[8 + w]; se0 += red[16 + w]; se1 += red[24 + w];
        }
        float lse0 = C_LN2 * (M2 + log2f(se0));
        float lse1 = C_LN2 * (M2 + log2f(se1));
        float c0 = lse0 - logf(Mb0);
        float c1 = lse1 - logf(Mb1);

        // KL: t0 = logu0 + 20*pk - 10*pq + c0 ; t1 = logu1 + 20*pq - 10*pk + c1
        float L0 = 0.f, L1 = 0.f;
#pragma unroll
        for (int i = 0; i < 6; i++) {
            int p2 = tid + 256 * i;
            if (p2 < KK / 2) {
                float2 eq = __bfloat1622float2(Eq[p2]);
                float2 ek = __bfloat1622float2(Ek[p2]);
                float2 pq = __bfloat1622float2(Pq[p2]);
                float2 pk = __bfloat1622float2(Pk[p2]);
                float t0x = fmaf(20.f, pk.x, fmaf(-10.f, pq.x, uu0[i].y + c0));
                float t0y = fmaf(20.f, pk.y, fmaf(-10.f, pq.y, uu0[i].w + c0));
                L0 += uu0[i].x * ek.x * t0x + uu0[i].z * ek.y * t0y;
                float t1x = fmaf(20.f, pq.x, fmaf(-10.f, pk.x, uu1[i].y + c1));
                float t1y = fmaf(20.f, pq.y, fmaf(-10.f, pk.y, uu1[i].w + c1));
                L1 += uu1[i].x * eq.x * t1x + uu1[i].z * eq.y * t1y;
            }
        }
#pragma unroll
        for (int o = 16; o > 0; o >>= 1) {
            L0 += __shfl_xor_sync(0xffffffffu, L0, o);
            L1 += __shfl_xor_sync(0xffffffffu, L1, o);
        }
        __syncthreads();
        if (lane == 0) { red[wid] = L0; red[8 + wid] = L1; }
        __syncthreads();
        if (tid == 0) {
            float Ls0 = 0.f, Ls1 = 0.f;
#pragma unroll
            for (int w = 0; w < 8; w++) { Ls0 += red[w]; Ls1 += red[8 + w]; }
            g_rowloss[r0 + j] = Ls0 / Mb0 + Ls1 / Mb1;
        }
        __syncthreads();
    }
}

__global__ void loss_reduce_kernel(float* out) {
    __shared__ float red[1024];
    int tid = threadIdx.x;
    float a = 0.0f;
    for (int b = tid; b < BB; b += 1024) a += g_rowloss[b];
    red[tid] = a; __syncthreads();
    for (int s = 512; s > 0; s >>= 1) {
        if (tid < s) red[tid] += red[tid + s];
        __syncthreads();
    }
    if (tid == 0) out[0] = red[0] / (float)(2 * BB);
}

// ---------------- launch ------------------------------------------------------
extern "C" void kernel_launch(void* const* d_in, const int* in_sizes, int n_in,
                              void* d_out, int out_size) {
    const float* q = (const float*)d_in[0];
    const float* k = (const float*)d_in[1];
    const float* c = (const float*)d_in[2];

    cudaFuncSetAttribute(gemm_mma_kernel, cudaFuncAttributeMaxDynamicSharedMemorySize,
                         GSTAGE * STAGE_BYTES);
    cudaFuncSetAttribute(final_pair_kernel, cudaFuncAttributeMaxDynamicSharedMemorySize,
                         FP_SMEM);

    l2norm_all_kernel<<<(2 * BB + KPAD) / 8, 256>>>(q, k, c);
    gemm_mma_kernel<<<(2 * BB / 128) * (KPAD / 256), 256, GSTAGE * STAGE_BYTES>>>();

    reduce_w_epi_kernel<<<dim3(6, 2), dim3(128, 4)>>>();       // u1
    fused_rc_kernel<<<NFB2, 256>>>();                          // v1; W2 partials
    reduce_w_fused_kernel<<<dim3(6, 2), dim3(128, 8)>>>(0);    // u2
    fused_rc_kernel<<<NFB2, 256>>>();                          // v2; W3 partials
    reduce_w_fused_kernel<<<dim3(6, 2), dim3(128, 8)>>>(1);    // u3 (+ g_ul)
    final_pair_kernel<<<BB / RFB, 256, FP_SMEM>>>();           // both losses per row
    loss_reduce_kernel<<<1, 1024>>>((float*)d_out);
}

// round 16
// speedup vs baseline: 1.3583x; 1.3583x over previous
#include <cuda_runtime.h>
#include <cuda_bf16.h>
#include <cstdint>

#define BB 16384
#define DD 256
#define KK 3000
#define KPAD 3072
#define KS 3072          // padded row stride of g_E (elements)
#define NFB2 1024        // fused row/col blocks over ALL 2B rows
#define RPB 32           // rows per fused block
#define RFB 8            // row-pairs per final block

#define C_EXP20 28.853900817779268f   // 20/ln2
#define C_EXP10 14.426950408889634f   // 10/ln2
#define C_LN2   0.6931471805599453f

// ---------------- device scratch -------------------------------------------
__device__ __align__(16) __nv_bfloat16 g_A2[(size_t)2 * BB * DD];
__device__ __align__(16) __nv_bfloat16 g_B2[(size_t)KPAD * DD];
__device__ __align__(16) __nv_bfloat16 g_E[(size_t)2 * BB * KS];  // exp(sim/eps) bf16
__device__ float g_partW[(size_t)256 * KPAD];    // per-GEMM-mtile col partials
__device__ float g_part2[(size_t)NFB2 * KPAD];   // fused-pass col partials
__device__ float g_W[2 * KPAD];                  // holds u = 1/(K*W)
__device__ float2 g_ul[2 * KK];                  // (u, log u) per loss (final iter)
__device__ float g_rowloss[BB];

// ---------------- helpers ----------------------------------------------------
static __device__ __forceinline__ float ex2f(float x) {
    float y; asm("ex2.approx.ftz.f32 %0, %1;" : "=f"(y) : "f"(x)); return y;
}
static __device__ __forceinline__ float lg2f(float x) {
    float y; asm("lg2.approx.ftz.f32 %0, %1;" : "=f"(y) : "f"(x)); return y;
}
static __device__ __forceinline__ uint32_t s2u(const void* p) {
    uint32_t a;
    asm("{ .reg .u64 t; cvta.to.shared.u64 t, %1; cvt.u32.u64 %0, t; }" : "=r"(a) : "l"(p));
    return a;
}

#define LDSM4(r, a)                                                             \
    asm volatile("ldmatrix.sync.aligned.m8n8.x4.shared.b16 {%0,%1,%2,%3}, [%4];" \
                 : "=r"((r)[0]), "=r"((r)[1]), "=r"((r)[2]), "=r"((r)[3]) : "r"(a))

#define MMA16816(d, a, b)                                                       \
    asm volatile(                                                               \
        "mma.sync.aligned.m16n8k16.row.col.f32.bf16.bf16.f32 "                  \
        "{%0,%1,%2,%3}, {%4,%5,%6,%7}, {%8,%9}, {%0,%1,%2,%3};"                 \
        : "+f"((d)[0]), "+f"((d)[1]), "+f"((d)[2]), "+f"((d)[3])                \
        : "r"((a)[0]), "r"((a)[1]), "r"((a)[2]), "r"((a)[3]),                   \
          "r"((b)[0]), "r"((b)[1]))

#define CPASYNC16(dst, src) \
    asm volatile("cp.async.cg.shared.global [%0], [%1], 16;" :: "r"(dst), "l"(src))
#define CP_COMMIT()  asm volatile("cp.async.commit_group;" ::: "memory")
#define CP_WAIT(n)   asm volatile("cp.async.wait_group %0;" :: "n"(n) : "memory")

// ---------------- 1) L2 normalize (q,k,c) + pad, one launch ------------------
__global__ void l2norm_all_kernel(const float* __restrict__ q,
                                  const float* __restrict__ k,
                                  const float* __restrict__ c) {
    int row  = blockIdx.x * 8 + (threadIdx.x >> 5);
    int lane = threadIdx.x & 31;
    if (row >= 2 * BB + KPAD) return;

    const float* src;
    __nv_bfloat16* dst;
    if (row < BB)            { src = q + (size_t)row * DD;            dst = g_A2 + (size_t)row * DD; }
    else if (row < 2 * BB)   { src = k + (size_t)(row - BB) * DD;     dst = g_A2 + (size_t)row * DD; }
    else if (row < 2 * BB + KK) { src = c + (size_t)(row - 2 * BB) * DD; dst = g_B2 + (size_t)(row - 2 * BB) * DD; }
    else {
        dst = g_B2 + (size_t)(row - 2 * BB) * DD;
#pragma unroll
        for (int i = 0; i < 8; i++) dst[lane + 32 * i] = __float2bfloat16(0.0f);
        return;
    }
    float v[8]; float s = 0.0f;
#pragma unroll
    for (int i = 0; i < 8; i++) { v[i] = src[lane + 32 * i]; s += v[i] * v[i]; }
#pragma unroll
    for (int o = 16; o > 0; o >>= 1) s += __shfl_xor_sync(0xffffffffu, s, o);
    float inv = 1.0f / fmaxf(sqrtf(s), 1e-12f);
#pragma unroll
    for (int i = 0; i < 8; i++) dst[lane + 32 * i] = __float2bfloat16(v[i] * inv);
}

// ---------------- 2) GEMM 128x256 tile + fused epilogue (E, W1-partials) -----
#define GSTAGE 3
#define STAGE_BYTES 49152   // A 16KB + B 32KB
#define NIT (DD / 64)       // 4

__global__ __launch_bounds__(256) void gemm_mma_kernel() {
    extern __shared__ char smem[];
    const uint32_t sb = s2u(smem);
    const int tid = threadIdx.x;
    const int lane = tid & 31;
    const int wid = tid >> 5;
    const int wm = wid >> 2;
    const int wn = wid & 3;

    const int nTilesN = KPAD / 256;   // 12
    const int mBase = (int)(blockIdx.x / nTilesN) * 128;
    const int nBase = (int)(blockIdx.x % nTilesN) * 256;

    const __nv_bfloat16* gA = g_A2 + (size_t)mBase * DD;
    const __nv_bfloat16* gB = g_B2 + (size_t)nBase * DD;

    float acc[4][8][4] = {};

    auto load_stage = [&](int s, int kIter) {
        uint32_t so = sb + (uint32_t)s * STAGE_BYTES;
        int k0 = kIter * 64;
#pragma unroll
        for (int i = 0; i < 12; i++) {
            int q = tid + i * 256;
            int isB = (q >= 1024);
            int idx = isB ? (q - 1024) : q;
            int row = idx >> 3;
            int c = idx & 7;
            uint32_t dst = so + (isB ? 16384 : 0) + row * 128 + ((c ^ (row & 7)) << 4);
            const __nv_bfloat16* src = isB ? (gB + (size_t)row * DD + k0 + c * 8)
                                           : (gA + (size_t)row * DD + k0 + c * 8);
            CPASYNC16(dst, src);
        }
        CP_COMMIT();
    };

    load_stage(0, 0);
    load_stage(1, 1);

    for (int it = 0; it < NIT; it++) {
        if (it + 2 < NIT) CP_WAIT(1);
        else              CP_WAIT(0);
        __syncthreads();
        if (it + 2 < NIT) load_stage((it + 2) % GSTAGE, it + 2);

        uint32_t aB = sb + (uint32_t)(it % GSTAGE) * STAGE_BYTES;
        uint32_t bB = aB + 16384;
#pragma unroll
        for (int ks = 0; ks < 4; ks++) {
            uint32_t a[4][4], b[8][2];
            int cch = ks * 2 + (lane >> 4);
#pragma unroll
            for (int mi = 0; mi < 4; mi++) {
                int row = wm * 64 + mi * 16 + (lane & 15);
                uint32_t addr = aB + row * 128 + ((cch ^ (row & 7)) << 4);
                LDSM4(a[mi], addr);
            }
#pragma unroll
            for (int nj = 0; nj < 4; nj++) {
                int row = wn * 64 + nj * 16 + (lane & 15);
                uint32_t addr = bB + row * 128 + ((cch ^ (row & 7)) << 4);
                uint32_t r4[4];
                LDSM4(r4, addr);
                b[nj * 2][0]     = r4[0]; b[nj * 2][1]     = r4[2];
                b[nj * 2 + 1][0] = r4[1]; b[nj * 2 + 1][1] = r4[3];
            }
#pragma unroll
            for (int mi = 0; mi < 4; mi++)
#pragma unroll
                for (int ni = 0; ni < 8; ni++)
                    MMA16816(acc[mi][ni], a[mi], b[ni]);
        }
        __syncthreads();
    }

    // fused epilogue: E bf16 (zero-padded cols) + per-tile column sums of E
    float* cs = (float*)smem;   // [2][256]
    float cp0[8], cp1[8];
#pragma unroll
    for (int ni = 0; ni < 8; ni++) { cp0[ni] = 0.f; cp1[ni] = 0.f; }

#pragma unroll
    for (int ni = 0; ni < 8; ni++) {
        int gn = nBase + wn * 64 + ni * 8 + (lane & 3) * 2;
        bool ok = (gn < KK);
#pragma unroll
        for (int mi = 0; mi < 4; mi++) {
            int gm = mBase + wm * 64 + mi * 16 + (lane >> 2);
            float e0 = ex2f(acc[mi][ni][0] * C_EXP20), e1 = ex2f(acc[mi][ni][1] * C_EXP20);
            float e2 = ex2f(acc[mi][ni][2] * C_EXP20), e3 = ex2f(acc[mi][ni][3] * C_EXP20);
            if (!ok) { e0 = e1 = e2 = e3 = 0.f; }
            __nv_bfloat162 eh0 = __floats2bfloat162_rn(e0, e1);
            __nv_bfloat162 eh1 = __floats2bfloat162_rn(e2, e3);
            *(uint32_t*)&g_E[(size_t)gm * KS + gn]       = *(uint32_t*)&eh0;
            *(uint32_t*)&g_E[(size_t)(gm + 8) * KS + gn] = *(uint32_t*)&eh1;
            cp0[ni] += e0 + e2;
            cp1[ni] += e1 + e3;
        }
    }
#pragma unroll
    for (int ni = 0; ni < 8; ni++) {
#pragma unroll
        for (int o = 4; o < 32; o <<= 1) {
            cp0[ni] += __shfl_xor_sync(0xffffffffu, cp0[ni], o);
            cp1[ni] += __shfl_xor_sync(0xffffffffu, cp1[ni], o);
        }
        if (lane < 4) {
            cs[wm * 256 + wn * 64 + ni * 8 + lane * 2]     = cp0[ni];
            cs[wm * 256 + wn * 64 + ni * 8 + lane * 2 + 1] = cp1[ni];
        }
    }
    __syncthreads();
    {
        int mtile = (int)(blockIdx.x / nTilesN);
        g_partW[(size_t)mtile * KPAD + nBase + tid] = cs[tid] + cs[256 + tid];
    }
}

// ---------------- 3) slab reductions (write u = 1/(K*W)) ---------------------
__global__ void reduce_w_epi_kernel() {   // grid (6,2), block (128,4)
    int l = blockIdx.y;
    int halfStart = (l == 0) ? 128 : 0;
    int tx = threadIdx.x, ty = threadIdx.y;
    int k4 = (blockIdx.x * 128 + tx) * 4;
    __shared__ float4 sm[4][128];
    float4 s = make_float4(0.f, 0.f, 0.f, 0.f);
    if (k4 < KK) {
        const float* base = g_partW + (size_t)(halfStart + ty * 32) * KPAD + k4;
#pragma unroll 8
        for (int i = 0; i < 32; i++) {
            float4 p = *(const float4*)(base + (size_t)i * KPAD);
            s.x += p.x; s.y += p.y; s.z += p.z; s.w += p.w;
        }
    }
    sm[ty][tx] = s;
    __syncthreads();
    if (ty == 0 && k4 < KK) {
#pragma unroll
        for (int w = 1; w < 4; w++) {
            float4 p = sm[w][tx];
            s.x += p.x; s.y += p.y; s.z += p.z; s.w += p.w;
        }
        float4 u = make_float4(1.0f / ((float)KK * s.x), 1.0f / ((float)KK * s.y),
                               1.0f / ((float)KK * s.z), 1.0f / ((float)KK * s.w));
        *(float4*)&g_W[l * KPAD + k4] = u;
    }
}

__global__ void reduce_w_fused_kernel(int writeU) {   // grid (6,2), block (128,8)
    int l = blockIdx.y;
    int slabStart = (l == 0) ? 512 : 0;
    int tx = threadIdx.x, ty = threadIdx.y;
    int k4 = (blockIdx.x * 128 + tx) * 4;
    __shared__ float4 sm[8][128];
    float4 s = make_float4(0.f, 0.f, 0.f, 0.f);
    if (k4 < KK) {
        const float* base = g_part2 + (size_t)(slabStart + ty * 64) * KPAD + k4;
#pragma unroll 8
        for (int i = 0; i < 64; i++) {
            float4 p = *(const float4*)(base + (size_t)i * KPAD);
            s.x += p.x; s.y += p.y; s.z += p.z; s.w += p.w;
        }
    }
    sm[ty][tx] = s;
    __syncthreads();
    if (ty == 0 && k4 < KK) {
#pragma unroll
        for (int w = 1; w < 8; w++) {
            float4 p = sm[w][tx];
            s.x += p.x; s.y += p.y; s.z += p.z; s.w += p.w;
        }
        float u0 = 1.0f / ((float)KK * s.x), u1 = 1.0f / ((float)KK * s.y);
        float u2 = 1.0f / ((float)KK * s.z), u3 = 1.0f / ((float)KK * s.w);
        *(float4*)&g_W[l * KPAD + k4] = make_float4(u0, u1, u2, u3);
        if (writeU) {
            g_ul[l * KK + k4]     = make_float2(u0, logf(u0));
            g_ul[l * KK + k4 + 1] = make_float2(u1, logf(u1));
            g_ul[l * KK + k4 + 2] = make_float2(u2, logf(u2));
            g_ul[l * KK + k4 + 3] = make_float2(u3, logf(u3));
        }
    }
}

// ---------------- 4) fused row+col pass: register-prefetch pipeline ----------
__global__ __launch_bounds__(256) void fused_rc_kernel() {
    __shared__ __nv_bfloat162 su2[KS / 2];                   // 6 KB
    __shared__ __align__(16) __nv_bfloat16 stage[4 * KS];    // 24 KB
    __shared__ float smw[8];
    __shared__ float sv[4];
    int tid = threadIdx.x, lane = tid & 31, wid = tid >> 5;
    int rowInR = wid >> 1;
    int half = wid & 1;
    int rbase = (int)blockIdx.x * RPB;
    int l = (rbase >= BB) ? 0 : 1;
    const float* U = g_W + (size_t)l * KPAD;
    for (int i = tid; i < KS / 2; i += 256) {
        float a = (2 * i < KK) ? U[2 * i] : 0.f;
        float b = (2 * i + 1 < KK) ? U[2 * i + 1] : 0.f;
        su2[i] = __floats2bfloat162_rn(a, b);
    }

    float acc[12];
#pragma unroll
    for (int i = 0; i < 12; i++) acc[i] = 0.f;

    uint4 v[6];
    {
        const __nv_bfloat16* row = g_E + (size_t)(rbase + rowInR) * KS + half * 1536;
#pragma unroll
        for (int j = 0; j < 6; j++) v[j] = *(const uint4*)(row + (lane + j * 32) * 8);
    }
    __syncthreads();

    for (int r = 0; r < RPB / 4; r++) {
        float m = 0.f;
#pragma unroll
        for (int j = 0; j < 6; j++) {
            int eo = (lane + j * 32) * 8;
            *(uint4*)&stage[rowInR * KS + half * 1536 + eo] = v[j];
            const __nv_bfloat162* h = (const __nv_bfloat162*)&v[j];
            const __nv_bfloat162* up = &su2[(half * 1536 + eo) >> 1];
            uint2 ur0 = *(const uint2*)up;
            uint2 ur1 = *(const uint2*)(up + 2);
#pragma unroll
            for (int t = 0; t < 4; t++) {
                float2 e = __bfloat1622float2(h[t]);
                uint32_t ub = (t < 2) ? ((t == 0) ? ur0.x : ur0.y)
                                      : ((t == 2) ? ur1.x : ur1.y);
                float2 u = __bfloat1622float2(*(__nv_bfloat162*)&ub);
                m += e.x * u.x + e.y * u.y;
            }
        }
#pragma unroll
        for (int o = 16; o > 0; o >>= 1) m += __shfl_xor_sync(0xffffffffu, m, o);
        if (lane == 0) smw[wid] = m;

        if (r + 1 < RPB / 4) {
            const __nv_bfloat16* row =
                g_E + (size_t)(rbase + (r + 1) * 4 + rowInR) * KS + half * 1536;
#pragma unroll
            for (int j = 0; j < 6; j++) v[j] = *(const uint4*)(row + (lane + j * 32) * 8);
        }
        __syncthreads();
        if (tid < 4) sv[tid] = 1.0f / ((float)BB * (smw[2 * tid] + smw[2 * tid + 1]));
        __syncthreads();

#pragma unroll
        for (int rr = 0; rr < 4; rr++) {
            float vv = sv[rr];
            const __nv_bfloat16* sp = &stage[rr * KS + tid * 12];
#pragma unroll
            for (int j = 0; j < 3; j++) {
                uint2 raw = *(const uint2*)(sp + j * 4);
                float2 e0 = __bfloat1622float2(*(__nv_bfloat162*)&raw.x);
                float2 e1 = __bfloat1622float2(*(__nv_bfloat162*)&raw.y);
                acc[j * 4 + 0] += vv * e0.x;
                acc[j * 4 + 1] += vv * e0.y;
                acc[j * 4 + 2] += vv * e1.x;
                acc[j * 4 + 3] += vv * e1.y;
            }
        }
        __syncthreads();
    }

    float* dst = &g_part2[(size_t)blockIdx.x * KPAD + tid * 12];
    *(float4*)(dst)     = make_float4(acc[0], acc[1], acc[2], acc[3]);
    *(float4*)(dst + 4) = make_float4(acc[4], acc[5], acc[6], acc[7]);
    *(float4*)(dst + 8) = make_float4(acc[8], acc[9], acc[10], acc[11]);
}

// ---------------- 5) final: SINGLE-PASS (reassociated KL), double-buffered ---
// rowloss = Sa0/Mb0 + lse0 - ln(Mb0) + Sa1/Mb1 + lse1 - ln(Mb1)
// Sa0 = sum u0*ek*(logu0 + ln2*lk - 0.5*ln2*lq); Mb0 = sum u0*ek;
// s0 = sum 2^(0.5*lq - M2); lse0 = ln2*(M2 + log2 s0).  (loss1 mirrored)
#define FP_SEG 6144              // bytes per row (KS bf16)
#define FP_BUF (2 * FP_SEG)      // Eq | Ek
#define FP_SMEM (2 * FP_BUF)     // 24576

__global__ __launch_bounds__(256) void final_pair_kernel() {
    extern __shared__ char fsm[];
    __shared__ float red[48];
    int tid = threadIdx.x, lane = tid & 31, wid = tid >> 5;
    int r0 = (int)blockIdx.x * RFB;

    float4 uu0[6], uu1[6];
    const float4* ulp0 = (const float4*)(g_ul);
    const float4* ulp1 = (const float4*)(g_ul + KK);
#pragma unroll
    for (int i = 0; i < 6; i++) {
        int p2 = tid + 256 * i;
        bool in = (p2 < KK / 2);
        uu0[i] = in ? ulp0[p2] : make_float4(0.f, 0.f, 0.f, 0.f);
        uu1[i] = in ? ulp1[p2] : make_float4(0.f, 0.f, 0.f, 0.f);
    }
    const float M2 = C_EXP10;

    auto issueF = [&](int j, int buf) {
        int rr = r0 + j;
        const char* sq = (const char*)(g_E + (size_t)rr * KS);
        const char* sk = (const char*)(g_E + (size_t)(BB + rr) * KS);
        uint32_t d = s2u(fsm) + (uint32_t)buf * FP_BUF;
#pragma unroll
        for (int i = 0; i < 3; i++) {
            int c = tid + 256 * i;        // 0..767; 384 16B chunks per row
            if (c < 384) CPASYNC16(d + c * 16, sq + c * 16);
            else         CPASYNC16(d + FP_SEG + (c - 384) * 16, sk + (c - 384) * 16);
        }
        CP_COMMIT();
    };

    issueF(0, 0);

    for (int j = 0; j < RFB; j++) {
        if (j + 1 < RFB) { issueF(j + 1, (j + 1) & 1); CP_WAIT(1); }
        else             { CP_WAIT(0); }
        __syncthreads();
        const char* buf = fsm + (size_t)(j & 1) * FP_BUF;
        const __nv_bfloat162* Eq = (const __nv_bfloat162*)(buf);
        const __nv_bfloat162* Ek = (const __nv_bfloat162*)(buf + FP_SEG);

        float mb0 = 0.f, mb1 = 0.f, s0 = 0.f, s1 = 0.f, sa0 = 0.f, sa1 = 0.f;
#pragma unroll
        for (int i = 0; i < 6; i++) {
            int p2 = tid + 256 * i;
            if (p2 < KK / 2) {
                float2 eq = __bfloat1622float2(Eq[p2]);
                float2 ek = __bfloat1622float2(Ek[p2]);
                float lqx = lg2f(eq.x), lqy = lg2f(eq.y);
                float lkx = lg2f(ek.x), lky = lg2f(ek.y);
                float w0x = uu0[i].x * ek.x, w0y = uu0[i].z * ek.y;
                float w1x = uu1[i].x * eq.x, w1y = uu1[i].z * eq.y;
                mb0 += w0x + w0y;
                mb1 += w1x + w1y;
                s0 += ex2f(fmaf(0.5f, lqx, -M2)) + ex2f(fmaf(0.5f, lqy, -M2));
                s1 += ex2f(fmaf(0.5f, lkx, -M2)) + ex2f(fmaf(0.5f, lky, -M2));
                sa0 += w0x * fmaf(C_LN2, fmaf(-0.5f, lqx, lkx), uu0[i].y)
                     + w0y * fmaf(C_LN2, fmaf(-0.5f, lqy, lky), uu0[i].w);
                sa1 += w1x * fmaf(C_LN2, fmaf(-0.5f, lkx, lqx), uu1[i].y)
                     + w1y * fmaf(C_LN2, fmaf(-0.5f, lky, lqy), uu1[i].w);
            }
        }
#pragma unroll
        for (int o = 16; o > 0; o >>= 1) {
            mb0 += __shfl_xor_sync(0xffffffffu, mb0, o);
            mb1 += __shfl_xor_sync(0xffffffffu, mb1, o);
            s0  += __shfl_xor_sync(0xffffffffu, s0, o);
            s1  += __shfl_xor_sync(0xffffffffu, s1, o);
            sa0 += __shfl_xor_sync(0xffffffffu, sa0, o);
            sa1 += __shfl_xor_sync(0xffffffffu, sa1, o);
        }
        if (lane == 0) {
            red[wid] = mb0; red[8 + wid] = mb1; red[16 + wid] = s0;
            red[24 + wid] = s1; red[32 + wid] = sa0; red[40 + wid] = sa1;
        }
        __syncthreads();
        if (tid == 0) {
            float Mb0 = 0.f, Mb1 = 0.f, S0 = 0.f, S1 = 0.f, Sa0 = 0.f, Sa1 = 0.f;
#pragma unroll
            for (int w = 0; w < 8; w++) {
                Mb0 += red[w]; Mb1 += red[8 + w]; S0 += red[16 + w];
                S1 += red[24 + w]; Sa0 += red[32 + w]; Sa1 += red[40 + w];
            }
            float lse0 = C_LN2 * (M2 + log2f(S0));
            float lse1 = C_LN2 * (M2 + log2f(S1));
            g_rowloss[r0 + j] = Sa0 / Mb0 + lse0 - logf(Mb0)
                              + Sa1 / Mb1 + lse1 - logf(Mb1);
        }
        __syncthreads();   // buffer reuse guard
    }
}

__global__ void loss_reduce_kernel(float* out) {
    __shared__ float red[1024];
    int tid = threadIdx.x;
    float a = 0.0f;
    for (int b = tid; b < BB; b += 1024) a += g_rowloss[b];
    red[tid] = a; __syncthreads();
    for (int s = 512; s > 0; s >>= 1) {
        if (tid < s) red[tid] += red[tid + s];
        __syncthreads();
    }
    if (tid == 0) out[0] = red[0] / (float)(2 * BB);
}

// ---------------- launch ------------------------------------------------------
extern "C" void kernel_launch(void* const* d_in, const int* in_sizes, int n_in,
                              void* d_out, int out_size) {
    const float* q = (const float*)d_in[0];
    const float* k = (const float*)d_in[1];
    const float* c = (const float*)d_in[2];

    cudaFuncSetAttribute(gemm_mma_kernel, cudaFuncAttributeMaxDynamicSharedMemorySize,
                         GSTAGE * STAGE_BYTES);
    cudaFuncSetAttribute(final_pair_kernel, cudaFuncAttributeMaxDynamicSharedMemorySize,
                         FP_SMEM);

    l2norm_all_kernel<<<(2 * BB + KPAD) / 8, 256>>>(q, k, c);
    gemm_mma_kernel<<<(2 * BB / 128) * (KPAD / 256), 256, GSTAGE * STAGE_BYTES>>>();

    reduce_w_epi_kernel<<<dim3(6, 2), dim3(128, 4)>>>();       // u1
    fused_rc_kernel<<<NFB2, 256>>>();                          // v1; W2 partials
    reduce_w_fused_kernel<<<dim3(6, 2), dim3(128, 8)>>>(0);    // u2
    fused_rc_kernel<<<NFB2, 256>>>();                          // v2; W3 partials
    reduce_w_fused_kernel<<<dim3(6, 2), dim3(128, 8)>>>(1);    // u3 (+ g_ul)
    final_pair_kernel<<<BB / RFB, 256, FP_SMEM>>>();           // both losses per row
    loss_reduce_kernel<<<1, 1024>>>((float*)d_out);
}

// round 17
// speedup vs baseline: 1.4097x; 1.0378x over previous
#include <cuda_runtime.h>
#include <cuda_bf16.h>
#include <cstdint>

#define BB 16384
#define DD 256
#define KK 3000
#define KPAD 3072
#define KS 3072          // padded row stride of g_E (elements)
#define NFB2 1024        // fused row/col blocks over ALL 2B rows
#define RPB 32           // rows per fused block
#define RFB 8            // row-pairs per final block

#define C_EXP20 28.853900817779268f   // 20/ln2
#define C_EXP10 14.426950408889634f   // 10/ln2
#define C_LN2   0.6931471805599453f

// ---------------- device scratch -------------------------------------------
__device__ __align__(16) __nv_bfloat16 g_A2[(size_t)2 * BB * DD];
__device__ __align__(16) __nv_bfloat16 g_B2[(size_t)KPAD * DD];
__device__ __align__(16) __nv_bfloat16 g_E[(size_t)2 * BB * KS];  // exp(sim/eps) bf16
__device__ float g_partW[(size_t)256 * KPAD];    // per-GEMM-mtile col partials
__device__ float g_part2[(size_t)NFB2 * KPAD];   // fused-pass col partials
__device__ float g_W[2 * KPAD];                  // holds u = 1/(K*W)
__device__ float2 g_ul[2 * KK];                  // (u, log u) per loss (final iter)
__device__ float g_rowloss[BB];

// ---------------- helpers ----------------------------------------------------
static __device__ __forceinline__ float ex2f(float x) {
    float y; asm("ex2.approx.ftz.f32 %0, %1;" : "=f"(y) : "f"(x)); return y;
}
static __device__ __forceinline__ float lg2f(float x) {
    float y; asm("lg2.approx.ftz.f32 %0, %1;" : "=f"(y) : "f"(x)); return y;
}
static __device__ __forceinline__ uint32_t s2u(const void* p) {
    uint32_t a;
    asm("{ .reg .u64 t; cvta.to.shared.u64 t, %1; cvt.u32.u64 %0, t; }" : "=r"(a) : "l"(p));
    return a;
}
// exact bf16x2 -> two f32 via bit ops (1 SHF + 1 LOP, no PRMT chain)
static __device__ __forceinline__ float bf_lo(uint32_t r) { return __uint_as_float(r << 16); }
static __device__ __forceinline__ float bf_hi(uint32_t r) { return __uint_as_float(r & 0xFFFF0000u); }

#define LDSM4(r, a)                                                             \
    asm volatile("ldmatrix.sync.aligned.m8n8.x4.shared.b16 {%0,%1,%2,%3}, [%4];" \
                 : "=r"((r)[0]), "=r"((r)[1]), "=r"((r)[2]), "=r"((r)[3]) : "r"(a))

#define MMA16816(d, a, b)                                                       \
    asm volatile(                                                               \
        "mma.sync.aligned.m16n8k16.row.col.f32.bf16.bf16.f32 "                  \
        "{%0,%1,%2,%3}, {%4,%5,%6,%7}, {%8,%9}, {%0,%1,%2,%3};"                 \
        : "+f"((d)[0]), "+f"((d)[1]), "+f"((d)[2]), "+f"((d)[3])                \
        : "r"((a)[0]), "r"((a)[1]), "r"((a)[2]), "r"((a)[3]),                   \
          "r"((b)[0]), "r"((b)[1]))

#define CPASYNC16(dst, src) \
    asm volatile("cp.async.cg.shared.global [%0], [%1], 16;" :: "r"(dst), "l"(src))
#define CP_COMMIT()  asm volatile("cp.async.commit_group;" ::: "memory")
#define CP_WAIT(n)   asm volatile("cp.async.wait_group %0;" :: "n"(n) : "memory")

// ---------------- 1) L2 normalize (q,k,c) + pad, one launch ------------------
__global__ void l2norm_all_kernel(const float* __restrict__ q,
                                  const float* __restrict__ k,
                                  const float* __restrict__ c) {
    int row  = blockIdx.x * 8 + (threadIdx.x >> 5);
    int lane = threadIdx.x & 31;
    if (row >= 2 * BB + KPAD) return;

    const float* src;
    __nv_bfloat16* dst;
    if (row < BB)            { src = q + (size_t)row * DD;            dst = g_A2 + (size_t)row * DD; }
    else if (row < 2 * BB)   { src = k + (size_t)(row - BB) * DD;     dst = g_A2 + (size_t)row * DD; }
    else if (row < 2 * BB + KK) { src = c + (size_t)(row - 2 * BB) * DD; dst = g_B2 + (size_t)(row - 2 * BB) * DD; }
    else {
        dst = g_B2 + (size_t)(row - 2 * BB) * DD;
#pragma unroll
        for (int i = 0; i < 8; i++) dst[lane + 32 * i] = __float2bfloat16(0.0f);
        return;
    }
    float v[8]; float s = 0.0f;
#pragma unroll
    for (int i = 0; i < 8; i++) { v[i] = src[lane + 32 * i]; s += v[i] * v[i]; }
#pragma unroll
    for (int o = 16; o > 0; o >>= 1) s += __shfl_xor_sync(0xffffffffu, s, o);
    float inv = 1.0f / fmaxf(sqrtf(s), 1e-12f);
#pragma unroll
    for (int i = 0; i < 8; i++) dst[lane + 32 * i] = __float2bfloat16(v[i] * inv);
}

// ---------------- 2) GEMM 128x256 tile + fused epilogue (E, W1-partials) -----
#define GSTAGE 3
#define STAGE_BYTES 49152   // A 16KB + B 32KB
#define NIT (DD / 64)       // 4

__global__ __launch_bounds__(256) void gemm_mma_kernel() {
    extern __shared__ char smem[];
    const uint32_t sb = s2u(smem);
    const int tid = threadIdx.x;
    const int lane = tid & 31;
    const int wid = tid >> 5;
    const int wm = wid >> 2;
    const int wn = wid & 3;

    const int nTilesN = KPAD / 256;   // 12
    const int mBase = (int)(blockIdx.x / nTilesN) * 128;
    const int nBase = (int)(blockIdx.x % nTilesN) * 256;

    const __nv_bfloat16* gA = g_A2 + (size_t)mBase * DD;
    const __nv_bfloat16* gB = g_B2 + (size_t)nBase * DD;

    float acc[4][8][4] = {};

    auto load_stage = [&](int s, int kIter) {
        uint32_t so = sb + (uint32_t)s * STAGE_BYTES;
        int k0 = kIter * 64;
#pragma unroll
        for (int i = 0; i < 12; i++) {
            int q = tid + i * 256;
            int isB = (q >= 1024);
            int idx = isB ? (q - 1024) : q;
            int row = idx >> 3;
            int c = idx & 7;
            uint32_t dst = so + (isB ? 16384 : 0) + row * 128 + ((c ^ (row & 7)) << 4);
            const __nv_bfloat16* src = isB ? (gB + (size_t)row * DD + k0 + c * 8)
                                           : (gA + (size_t)row * DD + k0 + c * 8);
            CPASYNC16(dst, src);
        }
        CP_COMMIT();
    };

    load_stage(0, 0);
    load_stage(1, 1);

    for (int it = 0; it < NIT; it++) {
        if (it + 2 < NIT) CP_WAIT(1);
        else              CP_WAIT(0);
        __syncthreads();
        if (it + 2 < NIT) load_stage((it + 2) % GSTAGE, it + 2);

        uint32_t aB = sb + (uint32_t)(it % GSTAGE) * STAGE_BYTES;
        uint32_t bB = aB + 16384;
#pragma unroll
        for (int ks = 0; ks < 4; ks++) {
            uint32_t a[4][4], b[8][2];
            int cch = ks * 2 + (lane >> 4);
#pragma unroll
            for (int mi = 0; mi < 4; mi++) {
                int row = wm * 64 + mi * 16 + (lane & 15);
                uint32_t addr = aB + row * 128 + ((cch ^ (row & 7)) << 4);
                LDSM4(a[mi], addr);
            }
#pragma unroll
            for (int nj = 0; nj < 4; nj++) {
                int row = wn * 64 + nj * 16 + (lane & 15);
                uint32_t addr = bB + row * 128 + ((cch ^ (row & 7)) << 4);
                uint32_t r4[4];
                LDSM4(r4, addr);
                b[nj * 2][0]     = r4[0]; b[nj * 2][1]     = r4[2];
                b[nj * 2 + 1][0] = r4[1]; b[nj * 2 + 1][1] = r4[3];
            }
#pragma unroll
            for (int mi = 0; mi < 4; mi++)
#pragma unroll
                for (int ni = 0; ni < 8; ni++)
                    MMA16816(acc[mi][ni], a[mi], b[ni]);
        }
        __syncthreads();
    }

    // fused epilogue: E bf16 (zero-padded cols) + per-tile column sums of E
    float* cs = (float*)smem;   // [2][256]
    float cp0[8], cp1[8];
#pragma unroll
    for (int ni = 0; ni < 8; ni++) { cp0[ni] = 0.f; cp1[ni] = 0.f; }

#pragma unroll
    for (int ni = 0; ni < 8; ni++) {
        int gn = nBase + wn * 64 + ni * 8 + (lane & 3) * 2;
        bool ok = (gn < KK);
#pragma unroll
        for (int mi = 0; mi < 4; mi++) {
            int gm = mBase + wm * 64 + mi * 16 + (lane >> 2);
            float e0 = ex2f(acc[mi][ni][0] * C_EXP20), e1 = ex2f(acc[mi][ni][1] * C_EXP20);
            float e2 = ex2f(acc[mi][ni][2] * C_EXP20), e3 = ex2f(acc[mi][ni][3] * C_EXP20);
            if (!ok) { e0 = e1 = e2 = e3 = 0.f; }
            __nv_bfloat162 eh0 = __floats2bfloat162_rn(e0, e1);
            __nv_bfloat162 eh1 = __floats2bfloat162_rn(e2, e3);
            *(uint32_t*)&g_E[(size_t)gm * KS + gn]       = *(uint32_t*)&eh0;
            *(uint32_t*)&g_E[(size_t)(gm + 8) * KS + gn] = *(uint32_t*)&eh1;
            cp0[ni] += e0 + e2;
            cp1[ni] += e1 + e3;
        }
    }
#pragma unroll
    for (int ni = 0; ni < 8; ni++) {
#pragma unroll
        for (int o = 4; o < 32; o <<= 1) {
            cp0[ni] += __shfl_xor_sync(0xffffffffu, cp0[ni], o);
            cp1[ni] += __shfl_xor_sync(0xffffffffu, cp1[ni], o);
        }
        if (lane < 4) {
            cs[wm * 256 + wn * 64 + ni * 8 + lane * 2]     = cp0[ni];
            cs[wm * 256 + wn * 64 + ni * 8 + lane * 2 + 1] = cp1[ni];
        }
    }
    __syncthreads();
    {
        int mtile = (int)(blockIdx.x / nTilesN);
        g_partW[(size_t)mtile * KPAD + nBase + tid] = cs[tid] + cs[256 + tid];
    }
}

// ---------------- 3) slab reductions (write u = 1/(K*W)) ---------------------
__global__ void reduce_w_epi_kernel() {   // grid (6,2), block (128,4)
    int l = blockIdx.y;
    int halfStart = (l == 0) ? 128 : 0;
    int tx = threadIdx.x, ty = threadIdx.y;
    int k4 = (blockIdx.x * 128 + tx) * 4;
    __shared__ float4 sm[4][128];
    float4 s = make_float4(0.f, 0.f, 0.f, 0.f);
    if (k4 < KK) {
        const float* base = g_partW + (size_t)(halfStart + ty * 32) * KPAD + k4;
#pragma unroll 8
        for (int i = 0; i < 32; i++) {
            float4 p = *(const float4*)(base + (size_t)i * KPAD);
            s.x += p.x; s.y += p.y; s.z += p.z; s.w += p.w;
        }
    }
    sm[ty][tx] = s;
    __syncthreads();
    if (ty == 0 && k4 < KK) {
#pragma unroll
        for (int w = 1; w < 4; w++) {
            float4 p = sm[w][tx];
            s.x += p.x; s.y += p.y; s.z += p.z; s.w += p.w;
        }
        float4 u = make_float4(1.0f / ((float)KK * s.x), 1.0f / ((float)KK * s.y),
                               1.0f / ((float)KK * s.z), 1.0f / ((float)KK * s.w));
        *(float4*)&g_W[l * KPAD + k4] = u;
    }
}

__global__ void reduce_w_fused_kernel(int writeU) {   // grid (6,2), block (128,8)
    int l = blockIdx.y;
    int slabStart = (l == 0) ? 512 : 0;
    int tx = threadIdx.x, ty = threadIdx.y;
    int k4 = (blockIdx.x * 128 + tx) * 4;
    __shared__ float4 sm[8][128];
    float4 s = make_float4(0.f, 0.f, 0.f, 0.f);
    if (k4 < KK) {
        const float* base = g_part2 + (size_t)(slabStart + ty * 64) * KPAD + k4;
#pragma unroll 8
        for (int i = 0; i < 64; i++) {
            float4 p = *(const float4*)(base + (size_t)i * KPAD);
            s.x += p.x; s.y += p.y; s.z += p.z; s.w += p.w;
        }
    }
    sm[ty][tx] = s;
    __syncthreads();
    if (ty == 0 && k4 < KK) {
#pragma unroll
        for (int w = 1; w < 8; w++) {
            float4 p = sm[w][tx];
            s.x += p.x; s.y += p.y; s.z += p.z; s.w += p.w;
        }
        float u0 = 1.0f / ((float)KK * s.x), u1 = 1.0f / ((float)KK * s.y);
        float u2 = 1.0f / ((float)KK * s.z), u3 = 1.0f / ((float)KK * s.w);
        *(float4*)&g_W[l * KPAD + k4] = make_float4(u0, u1, u2, u3);
        if (writeU) {
            g_ul[l * KK + k4]     = make_float2(u0, logf(u0));
            g_ul[l * KK + k4 + 1] = make_float2(u1, logf(u1));
            g_ul[l * KK + k4 + 2] = make_float2(u2, logf(u2));
            g_ul[l * KK + k4 + 3] = make_float2(u3, logf(u3));
        }
    }
}

// ---------------- 4) fused row+col pass: register-prefetch pipeline ----------
__global__ __launch_bounds__(256, 4) void fused_rc_kernel() {
    __shared__ __nv_bfloat162 su2[KS / 2];                   // 6 KB
    __shared__ __align__(16) __nv_bfloat16 stage[4 * KS];    // 24 KB
    __shared__ float smw[8];
    __shared__ float sv[4];
    int tid = threadIdx.x, lane = tid & 31, wid = tid >> 5;
    int rowInR = wid >> 1;
    int half = wid & 1;
    int rbase = (int)blockIdx.x * RPB;
    int l = (rbase >= BB) ? 0 : 1;
    const float* U = g_W + (size_t)l * KPAD;
    for (int i = tid; i < KS / 2; i += 256) {
        float a = (2 * i < KK) ? U[2 * i] : 0.f;
        float b = (2 * i + 1 < KK) ? U[2 * i + 1] : 0.f;
        su2[i] = __floats2bfloat162_rn(a, b);
    }

    float acc[12];
#pragma unroll
    for (int i = 0; i < 12; i++) acc[i] = 0.f;

    uint4 v[6];
    {
        const __nv_bfloat16* row = g_E + (size_t)(rbase + rowInR) * KS + half * 1536;
#pragma unroll
        for (int j = 0; j < 6; j++) v[j] = *(const uint4*)(row + (lane + j * 32) * 8);
    }
    __syncthreads();

    for (int r = 0; r < RPB / 4; r++) {
        float m = 0.f;
#pragma unroll
        for (int j = 0; j < 6; j++) {
            int eo = (lane + j * 32) * 8;
            *(uint4*)&stage[rowInR * KS + half * 1536 + eo] = v[j];
            const uint32_t* h = (const uint32_t*)&v[j];
            const uint32_t* up = (const uint32_t*)&su2[(half * 1536 + eo) >> 1];
            uint32_t u0 = up[0], u1 = up[1], u2 = up[2], u3 = up[3];
            m += bf_lo(h[0]) * bf_lo(u0) + bf_hi(h[0]) * bf_hi(u0)
               + bf_lo(h[1]) * bf_lo(u1) + bf_hi(h[1]) * bf_hi(u1)
               + bf_lo(h[2]) * bf_lo(u2) + bf_hi(h[2]) * bf_hi(u2)
               + bf_lo(h[3]) * bf_lo(u3) + bf_hi(h[3]) * bf_hi(u3);
        }
#pragma unroll
        for (int o = 16; o > 0; o >>= 1) m += __shfl_xor_sync(0xffffffffu, m, o);
        if (lane == 0) smw[wid] = m;

        if (r + 1 < RPB / 4) {
            const __nv_bfloat16* row =
                g_E + (size_t)(rbase + (r + 1) * 4 + rowInR) * KS + half * 1536;
#pragma unroll
            for (int j = 0; j < 6; j++) v[j] = *(const uint4*)(row + (lane + j * 32) * 8);
        }
        __syncthreads();
        if (tid < 4) sv[tid] = 1.0f / ((float)BB * (smw[2 * tid] + smw[2 * tid + 1]));
        __syncthreads();

#pragma unroll
        for (int rr = 0; rr < 4; rr++) {
            float vv = sv[rr];
            const __nv_bfloat16* sp = &stage[rr * KS + tid * 12];
#pragma unroll
            for (int j = 0; j < 3; j++) {
                uint2 raw = *(const uint2*)(sp + j * 4);
                acc[j * 4 + 0] += vv * bf_lo(raw.x);
                acc[j * 4 + 1] += vv * bf_hi(raw.x);
                acc[j * 4 + 2] += vv * bf_lo(raw.y);
                acc[j * 4 + 3] += vv * bf_hi(raw.y);
            }
        }
        __syncthreads();
    }

    float* dst = &g_part2[(size_t)blockIdx.x * KPAD + tid * 12];
    *(float4*)(dst)     = make_float4(acc[0], acc[1], acc[2], acc[3]);
    *(float4*)(dst + 4) = make_float4(acc[4], acc[5], acc[6], acc[7]);
    *(float4*)(dst + 8) = make_float4(acc[8], acc[9], acc[10], acc[11]);
}

// ---------------- 5) final: SINGLE-PASS (reassociated KL), double-buffered ---
#define FP_SEG 6144              // bytes per row (KS bf16)
#define FP_BUF (2 * FP_SEG)      // Eq | Ek
#define FP_SMEM (2 * FP_BUF)     // 24576

__global__ __launch_bounds__(256) void final_pair_kernel() {
    extern __shared__ char fsm[];
    __shared__ float red[48];
    int tid = threadIdx.x, lane = tid & 31, wid = tid >> 5;
    int r0 = (int)blockIdx.x * RFB;

    float4 uu0[6], uu1[6];
    const float4* ulp0 = (const float4*)(g_ul);
    const float4* ulp1 = (const float4*)(g_ul + KK);
#pragma unroll
    for (int i = 0; i < 6; i++) {
        int p2 = tid + 256 * i;
        bool in = (p2 < KK / 2);
        uu0[i] = in ? ulp0[p2] : make_float4(0.f, 0.f, 0.f, 0.f);
        uu1[i] = in ? ulp1[p2] : make_float4(0.f, 0.f, 0.f, 0.f);
    }
    const float M2 = C_EXP10;

    auto issueF = [&](int j, int buf) {
        int rr = r0 + j;
        const char* sq = (const char*)(g_E + (size_t)rr * KS);
        const char* sk = (const char*)(g_E + (size_t)(BB + rr) * KS);
        uint32_t d = s2u(fsm) + (uint32_t)buf * FP_BUF;
#pragma unroll
        for (int i = 0; i < 3; i++) {
            int c = tid + 256 * i;
            if (c < 384) CPASYNC16(d + c * 16, sq + c * 16);
            else         CPASYNC16(d + FP_SEG + (c - 384) * 16, sk + (c - 384) * 16);
        }
        CP_COMMIT();
    };

    issueF(0, 0);

    for (int j = 0; j < RFB; j++) {
        if (j + 1 < RFB) { issueF(j + 1, (j + 1) & 1); CP_WAIT(1); }
        else             { CP_WAIT(0); }
        __syncthreads();
        const char* buf = fsm + (size_t)(j & 1) * FP_BUF;
        const uint32_t* Eq = (const uint32_t*)(buf);
        const uint32_t* Ek = (const uint32_t*)(buf + FP_SEG);

        float mb0 = 0.f, mb1 = 0.f, s0 = 0.f, s1 = 0.f, sa0 = 0.f, sa1 = 0.f;
#pragma unroll
        for (int i = 0; i < 6; i++) {
            int p2 = tid + 256 * i;
            if (p2 < KK / 2) {
                uint32_t rq = Eq[p2], rk = Ek[p2];
                float eqx = bf_lo(rq), eqy = bf_hi(rq);
                float ekx = bf_lo(rk), eky = bf_hi(rk);
                float lqx = lg2f(eqx), lqy = lg2f(eqy);
                float lkx = lg2f(ekx), lky = lg2f(eky);
                float w0x = uu0[i].x * ekx, w0y = uu0[i].z * eky;
                float w1x = uu1[i].x * eqx, w1y = uu1[i].z * eqy;
                mb0 += w0x + w0y;
                mb1 += w1x + w1y;
                s0 += ex2f(fmaf(0.5f, lqx, -M2)) + ex2f(fmaf(0.5f, lqy, -M2));
                s1 += ex2f(fmaf(0.5f, lkx, -M2)) + ex2f(fmaf(0.5f, lky, -M2));
                sa0 += w0x * fmaf(C_LN2, fmaf(-0.5f, lqx, lkx), uu0[i].y)
                     + w0y * fmaf(C_LN2, fmaf(-0.5f, lqy, lky), uu0[i].w);
                sa1 += w1x * fmaf(C_LN2, fmaf(-0.5f, lkx, lqx), uu1[i].y)
                     + w1y * fmaf(C_LN2, fmaf(-0.5f, lky, lqy), uu1[i].w);
            }
        }
#pragma unroll
        for (int o = 16; o > 0; o >>= 1) {
            mb0 += __shfl_xor_sync(0xffffffffu, mb0, o);
            mb1 += __shfl_xor_sync(0xffffffffu, mb1, o);
            s0  += __shfl_xor_sync(0xffffffffu, s0, o);
            s1  += __shfl_xor_sync(0xffffffffu, s1, o);
            sa0 += __shfl_xor_sync(0xffffffffu, sa0, o);
            sa1 += __shfl_xor_sync(0xffffffffu, sa1, o);
        }
        if (lane == 0) {
            red[wid] = mb0; red[8 + wid] = mb1; red[16 + wid] = s0;
            red[24 + wid] = s1; red[32 + wid] = sa0; red[40 + wid] = sa1;
        }
        __syncthreads();
        if (tid == 0) {
            float Mb0 = 0.f, Mb1 = 0.f, S0 = 0.f, S1 = 0.f, Sa0 = 0.f, Sa1 = 0.f;
#pragma unroll
            for (int w = 0; w < 8; w++) {
                Mb0 += red[w]; Mb1 += red[8 + w]; S0 += red[16 + w];
                S1 += red[24 + w]; Sa0 += red[32 + w]; Sa1 += red[40 + w];
            }
            float lse0 = C_LN2 * (M2 + log2f(S0));
            float lse1 = C_LN2 * (M2 + log2f(S1));
            g_rowloss[r0 + j] = Sa0 / Mb0 + lse0 - logf(Mb0)
                              + Sa1 / Mb1 + lse1 - logf(Mb1);
        }
        __syncthreads();
    }
}

__global__ void loss_reduce_kernel(float* out) {
    __shared__ float red[1024];
    int tid = threadIdx.x;
    float a = 0.0f;
    for (int b = tid; b < BB; b += 1024) a += g_rowloss[b];
    red[tid] = a; __syncthreads();
    for (int s = 512; s > 0; s >>= 1) {
        if (tid < s) red[tid] += red[tid + s];
        __syncthreads();
    }
    if (tid == 0) out[0] = red[0] / (float)(2 * BB);
}

// ---------------- launch ------------------------------------------------------
extern "C" void kernel_launch(void* const* d_in, const int* in_sizes, int n_in,
                              void* d_out, int out_size) {
    const float* q = (const float*)d_in[0];
    const float* k = (const float*)d_in[1];
    const float* c = (const float*)d_in[2];

    cudaFuncSetAttribute(gemm_mma_kernel, cudaFuncAttributeMaxDynamicSharedMemorySize,
                         GSTAGE * STAGE_BYTES);
    cudaFuncSetAttribute(final_pair_kernel, cudaFuncAttributeMaxDynamicSharedMemorySize,
                         FP_SMEM);

    l2norm_all_kernel<<<(2 * BB + KPAD) / 8, 256>>>(q, k, c);
    gemm_mma_kernel<<<(2 * BB / 128) * (KPAD / 256), 256, GSTAGE * STAGE_BYTES>>>();

    reduce_w_epi_kernel<<<dim3(6, 2), dim3(128, 4)>>>();       // u1
    fused_rc_kernel<<<NFB2, 256>>>();                          // v1; W2 partials
    reduce_w_fused_kernel<<<dim3(6, 2), dim3(128, 8)>>>(0);    // u2
    fused_rc_kernel<<<NFB2, 256>>>();                          // v2; W3 partials
    reduce_w_fused_kernel<<<dim3(6, 2), dim3(128, 8)>>>(1);    // u3 (+ g_ul)
    final_pair_kernel<<<BB / RFB, 256, FP_SMEM>>>();           // both losses per row
    loss_reduce_kernel<<<1, 1024>>>((float*)d_out);
}